// round 17
// baseline (speedup 1.0000x reference)
#include <cuda_runtime.h>
#include <math_constants.h>

#define BB 2
#define NN 4096
#define DD 64
#define CMX 64
#define HH 8
#define KK 16
#define BN 8192            // BB*NN
#define NSPLIT 128         // wqk n-splits (32 n each)
#define FULLMASK 0xffffffffu

// ---------------- scratch (device globals; no allocation) ----------------
__device__ float4 g_p1[BN], g_p2[BN], g_p2w[BN];        // packed xyz + sqnorm
__device__ float  g_f1t[BN*DD], g_f2t[BN*DD];           // transposed features [B,N,D]
__device__ int    g_idxA[BN*KK], g_idxB[BN*KK], g_idxS[BN*KK];
__device__ float  g_part1[BN*CMX];                      // W0a·f1 + b0
__device__ float  g_pre2[BN*CMX];                       // W0b·f2[j] (no bias)
__device__ float  g_feat[BN*KK*CMX], g_featw[BN*KK*CMX];
__device__ float  g_wqkp[(size_t)NSPLIT*BB*KK*KK*CMX];  // [sp][b][k*16+l][c] (coalesced c)
__device__ float  g_rsum[BB*CMX*KK], g_csum[BB*CMX*KK];
__device__ float  g_cost[BN*CMX], g_costw[BN*CMX];      // [b,n,c] layout

// ---------------- prep: transpose planes (z=0..3) + pack xyz (z=4) ----------------
__global__ void prep_k(const float* __restrict__ pA,
                       const float* __restrict__ pB,
                       const float* __restrict__ x1,
                       const float* __restrict__ x2,
                       const float* __restrict__ x2w) {
    __shared__ float t[32][33];
    int z = blockIdx.z;
    if (z < 4) {
        int a = z >> 1;      // 0: points1, 1: points2
        int b = z & 1;
        const float* src = a ? pB : pA;
        float* dst       = a ? g_f2t : g_f1t;
        int n0 = blockIdx.x * 32, c0 = blockIdx.y * 32;
#pragma unroll
        for (int j = 0; j < 4; j++)
            t[threadIdx.y + 8*j][threadIdx.x] =
                src[((size_t)b*DD + c0 + threadIdx.y + 8*j)*NN + n0 + threadIdx.x];
        __syncthreads();
#pragma unroll
        for (int j = 0; j < 4; j++)
            dst[((size_t)b*NN + n0 + threadIdx.y + 8*j)*DD + c0 + threadIdx.x] =
                t[threadIdx.x][threadIdx.y + 8*j];
        return;
    }
    int fb = blockIdx.y*128 + blockIdx.x;
    if (fb >= 32) return;
    int tid = threadIdx.y*32 + threadIdx.x;
    int i = fb*256 + tid;
    int b = i >> 12, n = i & (NN - 1);
#pragma unroll
    for (int tt = 0; tt < 3; tt++) {
        const float* s = (tt == 0) ? x1 : (tt == 1) ? x2 : x2w;
        float4* d      = (tt == 0) ? g_p1 : (tt == 1) ? g_p2 : g_p2w;
        float x = s[(size_t)b*3*NN + n];
        float y = s[(size_t)b*3*NN + NN + n];
        float z3 = s[(size_t)b*3*NN + 2*NN + n];
        d[i] = make_float4(x, y, z3, x*x + y*y + z3*z3);
    }
}

// ---------------- fused: knn x3 (y=0,1,2; 2 warps/query) + part1 (y=3) + pre2 (y=4) ----------------
__global__ __launch_bounds__(256) void knn3_part1_k(const float* __restrict__ W0,
                                                    const float* __restrict__ b0) {
    __shared__ __align__(16) float w0s[64*68];
    __shared__ __align__(16) float buf[8][64];
    __shared__ float sd[4][16];
    __shared__ int   si[4][16];
    int w = threadIdx.x >> 5, lane = threadIdx.x & 31;

    if (blockIdx.y < 3) {
        int which = blockIdx.y;
        const float4* ref = (which == 0) ? g_p2 : (which == 1) ? g_p2w : g_p1;
        int* outIdx       = (which == 0) ? g_idxA : (which == 1) ? g_idxB : g_idxS;
        int ql = w >> 1;                    // query slot 0..3
        int h  = w & 1;                     // half 0/1
        int q  = blockIdx.x * 4 + ql;
        int b  = q >> 12;
        const float4* refb = ref + b*NN;
        float4 Q = g_p1[q];
        float nx = -2.f*Q.x, ny = -2.f*Q.y, nz = -2.f*Q.z;

        float vd = CUDART_INF_F; int vi = 0x7fffffff;
        float taud = CUDART_INF_F; int taui = 0x7fffffff;
        int base = h * (NN/2);
#pragma unroll 4
        for (int j = 0; j < NN/64; j++) {
            int gi = base + j*32 + lane;
            float4 R = __ldg(&refb[gi]);
            float d = fmaf(nx, R.x, fmaf(ny, R.y, fmaf(nz, R.z, Q.w + R.w)));
            bool acc = (d < taud) || (d == taud && gi < taui);
            unsigned m = __ballot_sync(FULLMASK, acc);
            while (m) {
                int src = __ffs(m) - 1; m &= m - 1;
                float xd = __shfl_sync(FULLMASK, d,  src);
                int   xi = __shfl_sync(FULLMASK, gi, src);
                if (xd > taud || (xd == taud && xi > taui)) continue;
                bool lt = (vd < xd) || (vd == xd && vi < xi);
                int pos = __popc(__ballot_sync(FULLMASK, lt) & 0xffffu);
                if (pos < 16) {
                    float pd = __shfl_up_sync(FULLMASK, vd, 1);
                    int   pi = __shfl_up_sync(FULLMASK, vi, 1);
                    if (lane < 16) {
                        if (lane == pos)      { vd = xd; vi = xi; }
                        else if (lane > pos)  { vd = pd; vi = pi; }
                    }
                    taud = __shfl_sync(FULLMASK, vd, 15);
                    taui = __shfl_sync(FULLMASK, vi, 15);
                }
            }
        }
        if (h == 1 && lane < 16) { sd[ql][lane] = vd; si[ql][lane] = vi; }
        __syncthreads();
        if (h == 0) {
            // exact merge of two sorted 16-lists: rank = own_pos + |other < mine|
            float md; int mi; int own;
            if (lane < 16) { md = vd; mi = vi; own = lane; }
            else           { md = sd[ql][lane-16]; mi = si[ql][lane-16]; own = lane-16; }
            int cnt = 0;
#pragma unroll
            for (int s = 0; s < 16; s++) {
                int srcl = (lane < 16) ? 16 + s : s;
                float od = __shfl_sync(FULLMASK, md, srcl);
                int   oi = __shfl_sync(FULLMASK, mi, srcl);
                cnt += ((od < md) || (od == md && oi < mi)) ? 1 : 0;
            }
            int rank = own + cnt;
            if (rank < 16) outIdx[q*KK + rank] = mi;
        }
        return;
    }
    if (blockIdx.x >= BN/8) return;
    int plane = blockIdx.y;
    const float* srcf = (plane == 3) ? g_f1t : g_f2t;
    float* dstp       = (plane == 3) ? g_part1 : g_pre2;
    int coff          = (plane == 3) ? 0 : 64;
    for (int t = threadIdx.x; t < 64*64; t += 256) {
        int o = t >> 6, c = t & 63;
        w0s[o*68 + c] = W0[o*131 + coff + c];
    }
    __syncthreads();
    int i = blockIdx.x*8 + w;
    buf[w][lane]      = srcf[(size_t)i*64 + lane];
    buf[w][lane + 32] = srcf[(size_t)i*64 + 32 + lane];
    __syncwarp();
    float a0 = (plane == 3) ? b0[lane]      : 0.f;
    float a1 = (plane == 3) ? b0[lane + 32] : 0.f;
#pragma unroll
    for (int c4 = 0; c4 < 16; c4++) {
        float4 wa = *(const float4*)&w0s[lane*68 + c4*4];
        float4 wb = *(const float4*)&w0s[(lane+32)*68 + c4*4];
        float4 f  = *(const float4*)&buf[w][c4*4];
        a0 = fmaf(wa.x, f.x, a0); a0 = fmaf(wa.y, f.y, a0);
        a0 = fmaf(wa.z, f.z, a0); a0 = fmaf(wa.w, f.w, a0);
        a1 = fmaf(wb.x, f.x, a1); a1 = fmaf(wb.y, f.y, a1);
        a1 = fmaf(wb.z, f.z, a1); a1 = fmaf(wb.w, f.w, a1);
    }
    dstp[(size_t)i*64 + lane]      = a0;
    dstp[(size_t)i*64 + 32 + lane] = a1;
}

// ---------------- MLP v5: warp per (a,i) group (16 rows); layer1 via part1+pre2+dir ----------------
__global__ __launch_bounds__(128) void mlp_k(const float* __restrict__ W0,
                                             const float* __restrict__ W1,
                                             const float* __restrict__ b1) {
    __shared__ __align__(16) float w1s[64*68];    // 17408B
    __shared__ float b1s[64];
    __shared__ __align__(16) float buf[4][16][68]; // 17408B
    int w = threadIdx.x >> 5, lane = threadIdx.x & 31;
    for (int t = threadIdx.x; t < 64*64; t += 128) {
        int o = t >> 6, c = t & 63;
        w1s[o*68 + c] = W1[t];
    }
    if (threadIdx.x < 64) b1s[threadIdx.x] = b1[threadIdx.x];
    __syncthreads();
    float wc0x = W0[lane*131 + 128], wc0y = W0[lane*131 + 129], wc0z = W0[lane*131 + 130];
    float wc1x = W0[(lane+32)*131 + 128], wc1y = W0[(lane+32)*131 + 129], wc1z = W0[(lane+32)*131 + 130];
    float b1a = b1s[lane], b1b = b1s[lane + 32];

    const int NGRP = BN * 2;   // 16384 groups: (array, i)
    for (int g = blockIdx.x*4 + w; g < NGRP; g += gridDim.x*4) {
        int a = g >> 13;             // 0: feat, 1: featw
        int i = g & (BN - 1);
        int jgq = 0; float dx = 0.f, dy = 0.f, dz = 0.f;
        if (lane < 16) {
            int jl = (a ? g_idxB : g_idxA)[i*16 + lane];
            jgq = (i & ~(NN - 1)) + jl;
            float4 Pr = a ? g_p2w[jgq] : g_p2[jgq];
            float4 Pq = g_p1[i];
            dx = Pr.x - Pq.x; dy = Pr.y - Pq.y; dz = Pr.z - Pq.z;
        }
        float pa0 = g_part1[(size_t)i*64 + lane];
        float pa1 = g_part1[(size_t)i*64 + 32 + lane];
        float q0[16], q1[16];
#pragma unroll
        for (int r = 0; r < 16; r++) {
            int jr = __shfl_sync(FULLMASK, jgq, r);
            q0[r] = __ldg(&g_pre2[(size_t)jr*64 + lane]);
            q1[r] = __ldg(&g_pre2[(size_t)jr*64 + 32 + lane]);
        }
#pragma unroll
        for (int r = 0; r < 16; r++) {
            float dxr = __shfl_sync(FULLMASK, dx, r);
            float dyr = __shfl_sync(FULLMASK, dy, r);
            float dzr = __shfl_sync(FULLMASK, dz, r);
            float v0 = pa0 + q0[r];
            v0 = fmaf(wc0x, dxr, v0); v0 = fmaf(wc0y, dyr, v0); v0 = fmaf(wc0z, dzr, v0);
            float v1 = pa1 + q1[r];
            v1 = fmaf(wc1x, dxr, v1); v1 = fmaf(wc1y, dyr, v1); v1 = fmaf(wc1z, dzr, v1);
            v0 = v0 >= 0.f ? v0 : 0.1f*v0;
            v1 = v1 >= 0.f ? v1 : 0.1f*v1;
            buf[w][r][lane]      = v0;
            buf[w][r][lane + 32] = v1;
        }
        __syncwarp();
        float o0[16], o1[16];
#pragma unroll
        for (int r = 0; r < 16; r++) { o0[r] = b1a; o1[r] = b1b; }
#pragma unroll 2
        for (int c4 = 0; c4 < 16; c4++) {
            float4 wa = *(const float4*)&w1s[lane*68 + c4*4];
            float4 wb = *(const float4*)&w1s[(lane+32)*68 + c4*4];
#pragma unroll
            for (int r = 0; r < 16; r++) {
                float4 f = *(const float4*)&buf[w][r][c4*4];
                o0[r] = fmaf(wa.x, f.x, o0[r]); o0[r] = fmaf(wa.y, f.y, o0[r]);
                o0[r] = fmaf(wa.z, f.z, o0[r]); o0[r] = fmaf(wa.w, f.w, o0[r]);
                o1[r] = fmaf(wb.x, f.x, o1[r]); o1[r] = fmaf(wb.y, f.y, o1[r]);
                o1[r] = fmaf(wb.z, f.z, o1[r]); o1[r] = fmaf(wb.w, f.w, o1[r]);
            }
        }
        float* dst = a ? g_featw : g_feat;
        size_t r2 = (size_t)i*16;
#pragma unroll
        for (int r = 0; r < 16; r++) {
            float v0 = o0[r] >= 0.f ? o0[r] : 0.1f*o0[r];
            float v1 = o1[r] >= 0.f ? o1[r] : 0.1f*o1[r];
            dst[(r2 + r)*64 + lane]      = v0;
            dst[(r2 + r)*64 + 32 + lane] = v1;
        }
        __syncwarp();
    }
}

// ---------------- wqk v5: NSPLIT=128 (32 n/block), 512 threads, coalesced stores ----------------
__global__ __launch_bounds__(512) void wqk_k() {
    __shared__ __align__(16) float sf[64][68];   // 4n x 16k rows of feat,  64 c each
    __shared__ __align__(16) float sw[64][68];   // 4n x 16l rows of featw
    int ns = blockIdx.x;                // 0..NSPLIT-1 (32 n each)
    int b  = blockIdx.y;
    int tid = threadIdx.x;
    int c  = tid & 63;                  // channel
    int kp = tid >> 6;                  // k-pair 0..7

    float acc[2][16];
#pragma unroll
    for (int r = 0; r < 2; r++)
#pragma unroll
        for (int l = 0; l < 16; l++) acc[r][l] = 0.f;

    for (int ch = 0; ch < 8; ch++) {             // chunks of 4 n
        int n0 = ns*32 + ch*4;
        size_t rowbase = ((size_t)(b*NN + n0))*16;   // first (n,k) row
        __syncthreads();
#pragma unroll
        for (int v = 0; v < 2; v++) {
            int idx = v*512 + tid;               // 0..1023
            int row = idx >> 4, cf = (idx & 15)*4;
            *(float4*)&sf[row][cf] = *(const float4*)&g_feat [(rowbase + row)*64 + cf];
            *(float4*)&sw[row][cf] = *(const float4*)&g_featw[(rowbase + row)*64 + cf];
        }
        __syncthreads();
#pragma unroll
        for (int n = 0; n < 4; n++) {
            float wreg[16];
#pragma unroll
            for (int l = 0; l < 16; l++) wreg[l] = sw[n*16 + l][c];
            float fr[2];
#pragma unroll
            for (int r = 0; r < 2; r++) fr[r] = sf[n*16 + kp*2 + r][c];
#pragma unroll
            for (int r = 0; r < 2; r++)
#pragma unroll
                for (int l = 0; l < 16; l++)
                    acc[r][l] = fmaf(fr[r], wreg[l], acc[r][l]);
        }
    }
    size_t obase = ((size_t)(ns*BB + b))*256*64;     // [sp][b][kl][c]
#pragma unroll
    for (int r = 0; r < 2; r++)
#pragma unroll
        for (int l = 0; l < 16; l++)
            g_wqkp[obase + (size_t)((kp*2 + r)*16 + l)*64 + c] = acc[r][l];
}

// ---------------- softmax + clip + row/col sums ----------------
__global__ void softmax_k() {
    int t = blockIdx.x*256 + threadIdx.x;     // <<<8,256>>> -> 2048 threads
    int k  = t & 15;
    int bc = t >> 4;                          // 0..127 = b*64+c
    if (bc >= BB*CMX) return;
    int b = bc >> 6, c = bc & 63;
    const float inv_sqrt3 = 0.57735026918962576f;
    float row[16];
#pragma unroll
    for (int l = 0; l < 16; l++) {
        float s = 0.f;
        for (int sp = 0; sp < NSPLIT; sp++)
            s += g_wqkp[((size_t)(sp*BB + b)*256 + k*16 + l)*64 + c];
        row[l] = s;
    }
    float m = row[0];
#pragma unroll
    for (int l = 1; l < 16; l++) m = fmaxf(m, row[l]);
    float sum = 0.f;
#pragma unroll
    for (int l = 0; l < 16; l++) { row[l] = expf(row[l] - m); sum += row[l]; }
    float inv = 1.f / sum;
    float rs = 0.f;
#pragma unroll
    for (int l = 0; l < 16; l++) {
        float v = fmaxf(row[l]*inv*inv_sqrt3, 1e-10f);
        rs += v; row[l] = v;
    }
    g_rsum[bc*16 + k] = rs;
#pragma unroll
    for (int l = 0; l < 16; l++) {
        float v = row[l];
        v += __shfl_xor_sync(0xffffffffu, v, 1);
        v += __shfl_xor_sync(0xffffffffu, v, 2);
        v += __shfl_xor_sync(0xffffffffu, v, 4);
        v += __shfl_xor_sync(0xffffffffu, v, 8);
        if (k == 0) g_csum[bc*16 + l] = v;
    }
}

// ---------------- cost/costw: [b,n,c] layout for coalesced gather later ----------------
__global__ __launch_bounds__(256) void cost_k() {
    int t = blockIdx.x*256 + threadIdx.x;    // BN*64 threads
    int i = t >> 6, c = t & 63;
    int b = i >> 12;
    const float* cs = &g_csum[(size_t)(b*64 + c)*16];
    const float* rs = &g_rsum[(size_t)(b*64 + c)*16];
    float a = 0.f, aw = 0.f;
#pragma unroll
    for (int l = 0; l < 16; l++) {
        a  = fmaf(g_feat [((size_t)i*16 + l)*64 + c], cs[l], a);
        aw = fmaf(g_featw[((size_t)i*16 + l)*64 + c], rs[l], aw);
    }
    g_cost[t] = a; g_costw[t] = aw;
}

// ---------------- WeightNet + gather + final contraction ----------------
__global__ __launch_bounds__(128) void final_k(
    const float* __restrict__ wW0, const float* __restrict__ wb0,
    const float* __restrict__ wg0, const float* __restrict__ wbe0,
    const float* __restrict__ wW1, const float* __restrict__ wb1,
    const float* __restrict__ wg1, const float* __restrict__ wbe1,
    const float* __restrict__ wW2, const float* __restrict__ wb2,
    const float* __restrict__ wg2, const float* __restrict__ wbe2,
    float* __restrict__ out) {
    __shared__ float grp[128*65];           // grouped rows, padded
    __shared__ float w0f[24], b0f[8], s0f[8], e0f[8];
    __shared__ float w1f[64], b1f[8], s1f[8], e1f[8];
    __shared__ float w2f[512], b2f[64], s2f[64], e2f[64];
    int tid = threadIdx.x;
    const float invs = 1.f / sqrtf(1.f + 1e-5f);
    if (tid < 24) w0f[tid] = wW0[tid];
    if (tid < 8) {
        b0f[tid] = wb0[tid]; s0f[tid] = wg0[tid]*invs; e0f[tid] = wbe0[tid];
        b1f[tid] = wb1[tid]; s1f[tid] = wg1[tid]*invs; e1f[tid] = wbe1[tid];
    }
    if (tid < 64) {
        w1f[tid] = wW1[tid];
        b2f[tid] = wb2[tid]; s2f[tid] = wg2[tid]*invs; e2f[tid] = wbe2[tid];
    }
    for (int t = tid; t < 512; t += 128) w2f[t] = wW2[t];

    int i0 = blockIdx.x * 8;
    int b = i0 >> 12;
    __syncthreads();
    for (int s = 0; s < 64; s++) {
        int e = s*128 + tid;
        int rowe = e >> 6, ce = e & 63;
        int ie = i0 + (rowe >> 4);
        int ke = rowe & 15;
        int je = g_idxS[ie*16 + ke];
        int jg = (b << 12) + je;
        grp[rowe*65 + ce] = g_cost[(size_t)jg*64 + ce] + g_costw[(size_t)jg*64 + ce];
    }
    __syncthreads();

    int nl = tid >> 4, k = tid & 15;
    int i = i0 + nl, n = i & (NN - 1);
    int j = g_idxS[i*16 + k];
    int jg = (b << 12) + j;
    float4 Pj = g_p1[jg], Pi = g_p1[i];
    float dx = Pj.x - Pi.x, dy = Pj.y - Pi.y, dz = Pj.z - Pi.z;
    float h0[8];
#pragma unroll
    for (int o = 0; o < 8; o++) {
        float z = b0f[o] + w0f[o*3]*dx + w0f[o*3+1]*dy + w0f[o*3+2]*dz;
        z = z*s0f[o] + e0f[o];
        h0[o] = fmaxf(z, 0.f);
    }
    float h1[8];
#pragma unroll
    for (int o = 0; o < 8; o++) {
        float z = b1f[o];
#pragma unroll
        for (int c = 0; c < 8; c++) z = fmaf(w1f[o*8 + c], h0[c], z);
        z = z*s1f[o] + e1f[o];
        h1[o] = fmaxf(z, 0.f);
    }
    int myrow = nl*16 + k;
    for (int c = 0; c < 64; c++) {
        float z = b2f[c];
#pragma unroll
        for (int o = 0; o < 8; o++) z = fmaf(w2f[c*8 + o], h1[o], z);
        z = fmaxf(z*s2f[c] + e2f[c], 0.f);
        float v = z * grp[myrow*65 + c];
        v += __shfl_xor_sync(0xffffffffu, v, 1);
        v += __shfl_xor_sync(0xffffffffu, v, 2);
        v += __shfl_xor_sync(0xffffffffu, v, 4);
        v += __shfl_xor_sync(0xffffffffu, v, 8);
        if (k == 0) out[((size_t)b*CMX + c)*NN + n] = v;
    }
}

// ---------------- launch ----------------
extern "C" void kernel_launch(void* const* d_in, const int* in_sizes, int n_in,
                              void* d_out, int out_size) {
    const float* xyz1    = (const float*)d_in[0];
    const float* xyz2    = (const float*)d_in[1];
    const float* xyz2w   = (const float*)d_in[2];
    const float* points1 = (const float*)d_in[3];
    const float* points2 = (const float*)d_in[4];
    const float* mlp_W0  = (const float*)d_in[5];
    const float* mlp_b0  = (const float*)d_in[6];
    const float* mlp_W1  = (const float*)d_in[7];
    const float* mlp_b1  = (const float*)d_in[8];
    const float* wn_W0   = (const float*)d_in[9];
    const float* wn_b0   = (const float*)d_in[10];
    const float* wn_g0   = (const float*)d_in[11];
    const float* wn_be0  = (const float*)d_in[12];
    const float* wn_W1   = (const float*)d_in[13];
    const float* wn_b1   = (const float*)d_in[14];
    const float* wn_g1   = (const float*)d_in[15];
    const float* wn_be1  = (const float*)d_in[16];
    const float* wn_W2   = (const float*)d_in[17];
    const float* wn_b2   = (const float*)d_in[18];
    const float* wn_g2   = (const float*)d_in[19];
    const float* wn_be2  = (const float*)d_in[20];
    float* out = (float*)d_out;

    prep_k<<<dim3(NN/32, DD/32, 5), dim3(32, 8)>>>(points1, points2, xyz1, xyz2, xyz2w);
    knn3_part1_k<<<dim3(BN/4, 5), 256>>>(mlp_W0, mlp_b0);
    mlp_k<<<2048, 128>>>(mlp_W0, mlp_W1, mlp_b1);
    wqk_k<<<dim3(NSPLIT, BB), 512>>>();
    softmax_k<<<8, 256>>>();
    cost_k<<<BN*64/256, 256>>>();
    final_k<<<BN/8, 128>>>(wn_W0, wn_b0, wn_g0, wn_be0,
                           wn_W1, wn_b1, wn_g1, wn_be1,
                           wn_W2, wn_b2, wn_g2, wn_be2, out);
}